// round 1
// baseline (speedup 1.0000x reference)
#include <cuda_runtime.h>

#define B_    16
#define N_    1024
#define TIN_  24
#define TO_   20
#define CIN_  32
#define C_    64
#define NT_   (N_*TO_)          // 20480  (== B_*C_*TO_ as well)

// ---------------- scratch (device globals; no allocs) ----------------
__device__ float g_tem20[B_*CIN_*NT_];   // sliced tem_embedding [B,32,N,20]
__device__ float g_y    [B_*C_*NT_];     // TC conv output       [B,64,N,20]
__device__ float g_qkv  [B_*192*NT_];    // q(0-63) k(64-127) v(128-191)
__device__ float g_att  [B_*C_*NT_];     // attention output
__device__ float g_x2t  [N_*20480];      // x2 node-major: [n][(b*64+c)*20+t]
__device__ float g_cat0 [B_*192*NT_];    // [x2, nc(A0), nc(A1)]
__device__ float g_cat1 [B_*192*NT_];    // [x2, nc(A2), nc(A3)]
__device__ float g_h01  [B_*128*NT_];    // h0 (0-63), h1 (64-127)
__device__ float g_u    [B_*C_*NT_];
__device__ float g_h0f  [B_*C_*NT_];
__device__ float g_h1f  [B_*C_*NT_];

// ---------------- tem slice: tem[..., 4:24] -> contiguous [B,32,N,20] ----------------
__global__ void k_slice_tem(const float* __restrict__ tem) {
    int i = blockIdx.x * 256 + threadIdx.x;           // exact multiple
    int t = i % TO_;
    int rest = i / TO_;                               // (b*32+c)*1024 + n
    g_tem20[i] = tem[rest * TIN_ + t + 4];
}

// ---------------- dilated temporal conv (1x3, dil 2) + bias + relu ----------------
#define NPB 4
__global__ __launch_bounds__(256) void k_tc(const float* __restrict__ x,
                                            const float* __restrict__ w,
                                            const float* __restrict__ bias) {
    __shared__ float xs[NPB][CIN_][TIN_];     // 4*32*24 floats
    __shared__ float ws_t[96*65];             // [k=ci*3+kt][o] padded
    __shared__ float bs[C_];
    int tid = threadIdx.x;
    int blk = blockIdx.x;                     // B*N/NPB = 4096
    int b  = blk / (N_/NPB);
    int n0 = (blk % (N_/NPB)) * NPB;

    for (int i = tid; i < C_*CIN_*3; i += 256) {
        int o = i / 96, k = i % 96;
        ws_t[k*65 + o] = w[i];
    }
    if (tid < C_) bs[tid] = bias[tid];
    for (int i = tid; i < NPB*CIN_*TIN_; i += 256) {
        int nn = i / (CIN_*TIN_);
        int r  = i % (CIN_*TIN_);
        int ci = r / TIN_, tt = r % TIN_;
        xs[nn][ci][tt] = x[((b*CIN_ + ci)*N_ + n0 + nn)*TIN_ + tt];
    }
    __syncthreads();

    int co = tid & 63, nn = tid >> 6;
    float acc[TO_];
#pragma unroll
    for (int t = 0; t < TO_; t++) acc[t] = bs[co];
    for (int ci = 0; ci < CIN_; ci++) {
        float w0 = ws_t[(ci*3 + 0)*65 + co];
        float w1 = ws_t[(ci*3 + 1)*65 + co];
        float w2 = ws_t[(ci*3 + 2)*65 + co];
        const float* xr = xs[nn][ci];
#pragma unroll
        for (int t = 0; t < TO_; t++)
            acc[t] += w0*xr[t] + w1*xr[t+2] + w2*xr[t+4];
    }
    int ob = ((b*C_ + co)*N_ + n0 + nn)*TO_;
#pragma unroll
    for (int t = 0; t < TO_; t++) g_y[ob + t] = fmaxf(acc[t], 0.f);
}

// ---------------- generic batched conv1x1 GEMM: out[b][chOff+m][j] ----------------
// C = act(bias + W[64,K] * X[b][K][20480]); X rows split across (X0,X1) at ksplit.
__global__ __launch_bounds__(256) void k_conv1x1(
    const float* __restrict__ W, const float* __restrict__ bias,
    const float* __restrict__ X0, int bs0,
    const float* __restrict__ X1, int bs1, int ksplit,
    int K, float* __restrict__ out, int outC, int chOff, int doRelu)
{
    __shared__ float Ws[16][65];
    __shared__ float Xs[16][132];
    int tid = threadIdx.x;
    int b   = blockIdx.z;
    int j0  = blockIdx.x * 128;
    int ty  = tid >> 4, tx = tid & 15;

    float acc[4][8];
#pragma unroll
    for (int i = 0; i < 4; i++)
#pragma unroll
        for (int j = 0; j < 8; j++) acc[i][j] = 0.f;

    int wm = tid >> 2, wk4 = (tid & 3) * 4;
    int xr0 = tid >> 5, xc = (tid & 31) * 4;

    for (int k0 = 0; k0 < K; k0 += 16) {
        __syncthreads();
        float4 w4 = *(const float4*)(&W[wm*K + k0 + wk4]);
        Ws[wk4+0][wm] = w4.x; Ws[wk4+1][wm] = w4.y;
        Ws[wk4+2][wm] = w4.z; Ws[wk4+3][wm] = w4.w;
#pragma unroll
        for (int rr = 0; rr < 2; rr++) {
            int r = xr0 + rr*8;
            int k = k0 + r;
            const float* src = (k < ksplit) ? (X0 + bs0*b + k*NT_)
                                            : (X1 + bs1*b + (k - ksplit)*NT_);
            *(float4*)(&Xs[r][xc]) = *(const float4*)(src + j0 + xc);
        }
        __syncthreads();
#pragma unroll
        for (int kk = 0; kk < 16; kk++) {
            float a[4], xv[8];
#pragma unroll
            for (int i = 0; i < 4; i++) a[i] = Ws[kk][ty*4 + i];
#pragma unroll
            for (int j = 0; j < 8; j++) xv[j] = Xs[kk][tx*8 + j];
#pragma unroll
            for (int i = 0; i < 4; i++)
#pragma unroll
                for (int j = 0; j < 8; j++) acc[i][j] += a[i]*xv[j];
        }
    }
#pragma unroll
    for (int i = 0; i < 4; i++) {
        int m = ty*4 + i;
        float bv = bias ? bias[m] : 0.f;
        int obase = (b*outC + chOff + m)*NT_ + j0 + tx*8;
#pragma unroll
        for (int j = 0; j < 8; j++) {
            float v = acc[i][j] + bv;
            if (doRelu) v = fmaxf(v, 0.f);
            out[obase + j] = v;
        }
    }
}

// ---------------- fused masked MHA: one warp per (b, head, n) ----------------
__global__ __launch_bounds__(256) void k_attn() {
    __shared__ float sbuf[8][880];   // per warp: q160 k160 v160 S400
    int warp = threadIdx.x >> 5, lane = threadIdx.x & 31;
    int g = blockIdx.x * 8 + warp;   // B*8*N = 131072
    int b = g >> 13;
    int h = (g >> 10) & 7;
    int n = g & 1023;
    float* q = sbuf[warp];
    float* k = q + 160;
    float* v = k + 160;
    float* S = v + 160;

    int base = (b*192)*NT_ + n*TO_;
    for (int idx = lane; idx < 160; idx += 32) {
        int d = idx / TO_, t = idx % TO_;
        int co = (h*8 + d)*NT_ + t;
        q[idx] = g_qkv[base + co];
        k[idx] = g_qkv[base + 64*NT_ + co];
        v[idx] = g_qkv[base + 128*NT_ + co];
    }
    __syncwarp();
    for (int idx = lane; idx < 400; idx += 32) {
        int t = idx / TO_, s = idx % TO_;
        if (s <= t) {
            float acc = 0.f;
#pragma unroll
            for (int d = 0; d < 8; d++) acc += q[d*TO_ + t] * k[d*TO_ + s];
            S[idx] = acc * 0.35355339059327373f;   // 1/sqrt(8)
        }
    }
    __syncwarp();
    if (lane < TO_) {
        int t = lane;
        float mx = -1e30f;
        for (int s = 0; s <= t; s++) mx = fmaxf(mx, S[t*TO_ + s]);
        float sum = 0.f;
        for (int s = 0; s <= t; s++) { float e = __expf(S[t*TO_ + s] - mx); S[t*TO_ + s] = e; sum += e; }
        float inv = 1.f / sum;
        for (int s = 0; s <= t; s++) S[t*TO_ + s] *= inv;
    }
    __syncwarp();
    int obase = (b*C_)*NT_ + n*TO_;
    for (int idx = lane; idx < 160; idx += 32) {
        int d = idx / TO_, t = idx % TO_;
        float acc = 0.f;
        for (int s = 0; s <= t; s++) acc += S[t*TO_ + s] * v[d*TO_ + s];
        g_att[obase + (h*8 + d)*NT_ + t] = acc;
    }
}

// ---------------- spread x2 (in g_cat0 ch0-63) into g_cat1 ch0-63 and g_x2t ----------------
__global__ void k_spread() {
    int i = blockIdx.x * 256 + threadIdx.x;       // B*64*NT exact
    int b = i / (C_*NT_);
    int r = i % (C_*NT_);
    int c = r / NT_, nt = r % NT_;
    float v = g_cat0[(b*192 + c)*NT_ + nt];
    g_cat1[(b*192 + c)*NT_ + nt] = v;
    int n = nt / TO_, t = nt % TO_;
    g_x2t[n*20480 + (b*C_ + c)*TO_ + t] = v;
}

// ---------------- nconv: Y[w][j] = sum_v A[w][v] * x2t[v][j], scattered to cat bufs ----------------
__global__ __launch_bounds__(256) void k_nconv(
    const float* __restrict__ A0, const float* __restrict__ A1,
    const float* __restrict__ A2, const float* __restrict__ A3)
{
    __shared__ float As[8][132];
    __shared__ float Xs[8][132];
    int z = blockIdx.z;
    const float* A = (z == 0) ? A0 : (z == 1) ? A1 : (z == 2) ? A2 : A3;
    float* dest = (z < 2) ? g_cat0 : g_cat1;
    int chBase = (z & 1) ? 128 : 64;

    int tid = threadIdx.x;
    int m0 = blockIdx.y * 128, j0 = blockIdx.x * 128;
    int ty = tid >> 4, tx = tid & 15;
    int am = tid >> 1, ak = (tid & 1) * 4;
    int xr = tid >> 5, xc = (tid & 31) * 4;

    float acc[8][8];
#pragma unroll
    for (int i = 0; i < 8; i++)
#pragma unroll
        for (int j = 0; j < 8; j++) acc[i][j] = 0.f;

    for (int k0 = 0; k0 < N_; k0 += 8) {
        __syncthreads();
        float4 a4 = *(const float4*)(&A[(m0 + am)*N_ + k0 + ak]);
        As[ak+0][am] = a4.x; As[ak+1][am] = a4.y;
        As[ak+2][am] = a4.z; As[ak+3][am] = a4.w;
        *(float4*)(&Xs[xr][xc]) = *(const float4*)(&g_x2t[(k0 + xr)*20480 + j0 + xc]);
        __syncthreads();
#pragma unroll
        for (int kk = 0; kk < 8; kk++) {
            float a[8], xv[8];
#pragma unroll
            for (int i = 0; i < 8; i++) a[i] = As[kk][ty*8 + i];
#pragma unroll
            for (int j = 0; j < 8; j++) xv[j] = Xs[kk][tx*8 + j];
#pragma unroll
            for (int i = 0; i < 8; i++)
#pragma unroll
                for (int j = 0; j < 8; j++) acc[i][j] += a[i]*xv[j];
        }
    }
#pragma unroll
    for (int j = 0; j < 8; j++) {
        int jj = j0 + tx*8 + j;
        int bc = jj / TO_, t = jj - bc*TO_;
        int bi = bc >> 6, ci = bc & 63;
        int obase = (bi*192 + chBase + ci)*NT_ + (m0 + ty*8)*TO_ + t;
#pragma unroll
        for (int i = 0; i < 8; i++)
            dest[obase + i*TO_] = acc[i][j];
    }
}

// ---------------- micro fusion: softmax over 2 graphs, final output ----------------
__global__ void k_fusion(float* __restrict__ out) {
    int p = blockIdx.x * 256 + threadIdx.x;       // B*NT exact
    int b = p / NT_, j = p % NT_;
    int base = b*C_*NT_ + j;
    float s0 = 0.f, s1 = 0.f;
    for (int c = 0; c < C_; c++) {
        float uu = g_u[base + c*NT_];
        s0 += g_h0f[base + c*NT_] * uu;
        s1 += g_h1f[base + c*NT_] * uu;
    }
    float m  = fmaxf(s0, s1);
    float e0 = __expf(s0 - m), e1 = __expf(s1 - m);
    float inv = 1.f / (e0 + e1);
    float a0 = e0 * inv, a1 = e1 * inv;
    for (int c = 0; c < C_; c++) {
        int o = base + c*NT_;
        out[o] = a0*g_h0f[o] + a1*g_h1f[o];
    }
}

// ---------------- launch ----------------
extern "C" void kernel_launch(void* const* d_in, const int* in_sizes, int n_in,
                              void* d_out, int out_size) {
    const float* x    = (const float*)d_in[0];
    const float* tem  = (const float*)d_in[1];
    const float* A0   = (const float*)d_in[2];
    const float* A1   = (const float*)d_in[3];
    const float* A2   = (const float*)d_in[4];
    const float* A3   = (const float*)d_in[5];
    const float* w_tc = (const float*)d_in[6];
    const float* b_tc = (const float*)d_in[7];
    const float* wq   = (const float*)d_in[8];
    const float* bq   = (const float*)d_in[9];
    const float* wk   = (const float*)d_in[10];
    const float* bk   = (const float*)d_in[11];
    const float* wv   = (const float*)d_in[12];
    const float* bv   = (const float*)d_in[13];
    const float* wo   = (const float*)d_in[14];
    const float* bo   = (const float*)d_in[15];
    const float* wg0  = (const float*)d_in[16];
    const float* bg0  = (const float*)d_in[17];
    const float* wg1  = (const float*)d_in[18];
    const float* bg1  = (const float*)d_in[19];
    const float* wadp = (const float*)d_in[20];
    const float* badp = (const float*)d_in[21];
    const float* w0f  = (const float*)d_in[22];
    float* out = (float*)d_out;

    float *p_tem20, *p_y, *p_qkv, *p_att, *p_cat0, *p_cat1, *p_h01, *p_u, *p_h0f, *p_h1f;
    cudaGetSymbolAddress((void**)&p_tem20, g_tem20);
    cudaGetSymbolAddress((void**)&p_y,     g_y);
    cudaGetSymbolAddress((void**)&p_qkv,   g_qkv);
    cudaGetSymbolAddress((void**)&p_att,   g_att);
    cudaGetSymbolAddress((void**)&p_cat0,  g_cat0);
    cudaGetSymbolAddress((void**)&p_cat1,  g_cat1);
    cudaGetSymbolAddress((void**)&p_h01,   g_h01);
    cudaGetSymbolAddress((void**)&p_u,     g_u);
    cudaGetSymbolAddress((void**)&p_h0f,   g_h0f);
    cudaGetSymbolAddress((void**)&p_h1f,   g_h1f);

    // 1. slice tem embedding
    k_slice_tem<<<(B_*CIN_*NT_)/256, 256>>>(tem);
    // 2. temporal conv + relu
    k_tc<<<B_*N_/NPB, 256>>>(x, w_tc, b_tc);
    // 3. Q, K, V  (K=96: y channels 0-63, tem20 64-95)
    dim3 gg(160, 1, B_);
    k_conv1x1<<<gg, 256>>>(wq, bq, p_y, C_*NT_, p_tem20, CIN_*NT_, 64, 96, p_qkv, 192,   0, 0);
    k_conv1x1<<<gg, 256>>>(wk, bk, p_y, C_*NT_, p_tem20, CIN_*NT_, 64, 96, p_qkv, 192,  64, 0);
    k_conv1x1<<<gg, 256>>>(wv, bv, p_y, C_*NT_, p_tem20, CIN_*NT_, 64, 96, p_qkv, 192, 128, 0);
    // 4. attention
    k_attn<<<B_*8*N_/8, 256>>>();
    // 5. WO + relu -> cat0 ch 0-63
    k_conv1x1<<<gg, 256>>>(wo, bo, p_att, C_*NT_, p_att, 0, 64, 64, p_cat0, 192, 0, 1);
    // 6. spread x2 into cat1 and node-major x2t
    k_spread<<<(B_*C_*NT_)/256, 256>>>();
    // 7. graph diffusion (4 GEMMs 1024 x 20480 x 1024)
    k_nconv<<<dim3(160, 8, 4), 256>>>(A0, A1, A2, A3);
    // 8. h0, h1 (K=192) + relu
    k_conv1x1<<<gg, 256>>>(wg0, bg0, p_cat0, 192*NT_, p_cat0, 0, 192, 192, p_h01, 128,  0, 1);
    k_conv1x1<<<gg, 256>>>(wg1, bg1, p_cat1, 192*NT_, p_cat1, 0, 192, 192, p_h01, 128, 64, 1);
    // 9. u (K=128 over [h0,h1])
    k_conv1x1<<<gg, 256>>>(wadp, badp, p_h01, 128*NT_, p_h01, 0, 128, 128, p_u, 64, 0, 0);
    // 10. h0f, h1f (w0f, no bias)
    k_conv1x1<<<gg, 256>>>(w0f, nullptr, p_h01,           128*NT_, p_h01, 0, 64, 64, p_h0f, 64, 0, 0);
    k_conv1x1<<<gg, 256>>>(w0f, nullptr, p_h01 + 64*NT_,  128*NT_, p_h01, 0, 64, 64, p_h1f, 64, 0, 0);
    // 11. fusion -> out
    k_fusion<<<(B_*NT_)/256, 256>>>(out);
}

// round 3
// speedup vs baseline: 1.9430x; 1.9430x over previous
#include <cuda_runtime.h>
#include <cuda_bf16.h>
#include <cstdint>

#define B_    16
#define N_    1024
#define TIN_  24
#define TO_   20
#define CIN_  32
#define C_    64
#define NT_   (N_*TO_)          // 20480

#if defined(__CUDA_ARCH_FEAT_SM103_ALL) || defined(__CUDA_ARCH_FEAT_SM100_ALL)
#define TC_PATH 1
#endif

// ---------------- scratch (device globals; no allocs) ----------------
__device__ float g_tem20[B_*CIN_*NT_];
__device__ float g_y    [B_*C_*NT_];
__device__ float g_qkv  [B_*192*NT_];    // qkv, later reused for [u|h0f|h1f]
__device__ float g_att  [B_*C_*NT_];
__device__ float g_cat0 [B_*192*NT_];
__device__ float g_cat1 [B_*192*NT_];
__device__ float g_h01  [B_*128*NT_];
__device__ float g_wqkv [192*96];
__device__ float g_bqkv [192];
__device__ float g_w3   [192*128];
__device__ float g_b3   [192];
__device__ __align__(256) __nv_bfloat16 g_Ah [4*1024*1024];
__device__ __align__(256) __nv_bfloat16 g_Al [4*1024*1024];
__device__ __align__(256) __nv_bfloat16 g_xth[20480*1024];   // [j][k=n]
__device__ __align__(256) __nv_bfloat16 g_xtl[20480*1024];

// ======================= PTX helpers =======================
__device__ __forceinline__ uint32_t smem_u32(const void* p) {
    uint32_t a;
    asm("{ .reg .u64 t; cvta.to.shared.u64 t, %1; cvt.u32.u64 %0, t; }" : "=r"(a) : "l"(p));
    return a;
}
__device__ __forceinline__ void cpa16(uint32_t dst, const void* src) {
    asm volatile("cp.async.cg.shared.global [%0], [%1], 16;" :: "r"(dst), "l"(src));
}
__device__ __forceinline__ void cpa_commit() { asm volatile("cp.async.commit_group;" ::: "memory"); }
__device__ __forceinline__ void cpa_wait1()  { asm volatile("cp.async.wait_group 1;" ::: "memory"); }
__device__ __forceinline__ void cpa_wait0()  { asm volatile("cp.async.wait_group 0;" ::: "memory"); }
#define SWZ(o) ((o) ^ (((o) >> 3) & 0x70))

#ifdef TC_PATH
__device__ __forceinline__ uint32_t elect1() {
    uint32_t p;
    asm volatile("{\n\t.reg .pred p;\n\telect.sync _|p, 0xFFFFFFFF;\n\tselp.b32 %0, 1, 0, p;\n\t}" : "=r"(p));
    return p;
}
#define MBARRIER_INIT(addr, cnt) \
    asm volatile("mbarrier.init.shared.b64 [%0], %1;" :: "r"(addr), "r"(cnt) : "memory")
#define MBARRIER_INVAL(addr) \
    asm volatile("mbarrier.inval.shared.b64 [%0];" :: "r"(addr) : "memory")
#define MBARRIER_WAIT_PARITY(mbar_smem_addr, phase_parity) do { \
    uint32_t _mbar = (uint32_t)(mbar_smem_addr); \
    uint32_t _parity = (uint32_t)(phase_parity); \
    uint32_t _done; \
    asm volatile("{\n\t.reg .pred p;\n\t" \
        "mbarrier.try_wait.parity.acquire.cta.shared::cta.b64 p, [%1], %2;\n\t" \
        "selp.b32 %0, 1, 0, p;\n\t}" : "=r"(_done) : "r"(_mbar), "r"(_parity) : "memory"); \
    if (!_done) { \
        asm volatile("{\n\t.reg .pred P1;\n\t" \
            "WAIT_LOOP_%=:\n\t" \
            "mbarrier.try_wait.parity.acquire.cta.shared::cta.b64 P1, [%0], %1, 0x989680;\n\t" \
            "@P1 bra.uni WAIT_DONE_%=;\n\t" \
            "bra.uni WAIT_LOOP_%=;\n\t" \
            "WAIT_DONE_%=:\n\t}" :: "r"(_mbar), "r"(_parity) : "memory"); \
    } \
} while(0)
#define TCGEN05_ALLOC(saddr, n) \
    asm volatile("tcgen05.alloc.cta_group::1.sync.aligned.shared::cta.b32 [%0], %1;" \
        :: "r"((uint32_t)(saddr)), "r"((uint32_t)(n)) : "memory")
#define TCGEN05_DEALLOC(tmem, n) \
    asm volatile("tcgen05.dealloc.cta_group::1.sync.aligned.b32 %0, %1;" :: "r"(tmem), "r"((uint32_t)(n)))
#define TCGEN05_RELINQ() \
    asm volatile("tcgen05.relinquish_alloc_permit.cta_group::1.sync.aligned;")
#define TCGEN05_COMMIT(mbar) \
    asm volatile("tcgen05.commit.cta_group::1.mbarrier::arrive::one.shared::cluster.b64 [%0];" \
        :: "r"((uint32_t)(mbar)) : "memory")
#define TCGEN05_FENCE_AFTER() asm volatile("tcgen05.fence::after_thread_sync;" ::: "memory")
#define TCGEN05_WAIT_LD() asm volatile("tcgen05.wait::ld.sync.aligned;" ::: "memory")
#define TCGEN05_LD_32X32B_X32(r, tmem_addr) \
    asm volatile("tcgen05.ld.sync.aligned.32x32b.x32.b32 " \
        "{%0, %1, %2, %3, %4, %5, %6, %7, %8, %9, %10, %11, %12, %13, %14, %15, " \
        " %16, %17, %18, %19, %20, %21, %22, %23, %24, %25, %26, %27, %28, %29, %30, %31}, [%32];" \
        : "=r"((r)[0]),  "=r"((r)[1]),  "=r"((r)[2]),  "=r"((r)[3]), \
          "=r"((r)[4]),  "=r"((r)[5]),  "=r"((r)[6]),  "=r"((r)[7]), \
          "=r"((r)[8]),  "=r"((r)[9]),  "=r"((r)[10]), "=r"((r)[11]), \
          "=r"((r)[12]), "=r"((r)[13]), "=r"((r)[14]), "=r"((r)[15]), \
          "=r"((r)[16]), "=r"((r)[17]), "=r"((r)[18]), "=r"((r)[19]), \
          "=r"((r)[20]), "=r"((r)[21]), "=r"((r)[22]), "=r"((r)[23]), \
          "=r"((r)[24]), "=r"((r)[25]), "=r"((r)[26]), "=r"((r)[27]), \
          "=r"((r)[28]), "=r"((r)[29]), "=r"((r)[30]), "=r"((r)[31]) \
        : "r"(tmem_addr))

__device__ __forceinline__ uint64_t make_desc(uint32_t addr) {
    return 0x4000404000010000ULL | (uint64_t)((addr >> 4) & 0x3FFF);
}
__device__ __forceinline__ void mma_f16_ss_cg1(uint32_t d, uint64_t a, uint64_t b,
                                               uint32_t idesc, bool acc) {
    uint32_t en = acc ? 1u : 0u;
    asm volatile("{\n\t.reg .pred p;\n\tsetp.ne.u32 p, %5, 0;\n\t"
        "tcgen05.mma.cta_group::1.kind::f16 [%0], %1, %2, %3, {%4, %4, %4, %4}, p;\n\t}"
        :: "r"(d), "l"(a), "l"(b), "r"(idesc), "r"(0u), "r"(en) : "memory");
}
// idesc: dtype F32, atype BF16, btype BF16, N=256, M=128
#define IDESC_NC 0x8400490u
#endif // TC_PATH

// ---------------- tem slice ----------------
__global__ void k_slice_tem(const float* __restrict__ tem) {
    int i = blockIdx.x * 256 + threadIdx.x;
    int t = i % TO_;
    int rest = i / TO_;
    g_tem20[i] = tem[rest * TIN_ + t + 4];
}

// ---------------- dilated temporal conv + relu ----------------
#define NPB 4
__global__ __launch_bounds__(256) void k_tc(const float* __restrict__ x,
                                            const float* __restrict__ w,
                                            const float* __restrict__ bias) {
    __shared__ float xs[NPB][CIN_][TIN_];
    __shared__ float ws_t[96*65];
    __shared__ float bs[C_];
    int tid = threadIdx.x;
    int blk = blockIdx.x;
    int b  = blk / (N_/NPB);
    int n0 = (blk % (N_/NPB)) * NPB;

    for (int i = tid; i < C_*CIN_*3; i += 256) {
        int o = i / 96, k = i % 96;
        ws_t[k*65 + o] = w[i];
    }
    if (tid < C_) bs[tid] = bias[tid];
    for (int i = tid; i < NPB*CIN_*TIN_; i += 256) {
        int nn = i / (CIN_*TIN_);
        int r  = i % (CIN_*TIN_);
        int ci = r / TIN_, tt = r % TIN_;
        xs[nn][ci][tt] = x[((b*CIN_ + ci)*N_ + n0 + nn)*TIN_ + tt];
    }
    __syncthreads();

    int co = tid & 63, nn = tid >> 6;
    float acc[TO_];
#pragma unroll
    for (int t = 0; t < TO_; t++) acc[t] = bs[co];
    for (int ci = 0; ci < CIN_; ci++) {
        float w0 = ws_t[(ci*3 + 0)*65 + co];
        float w1 = ws_t[(ci*3 + 1)*65 + co];
        float w2 = ws_t[(ci*3 + 2)*65 + co];
        const float* xr = xs[nn][ci];
#pragma unroll
        for (int t = 0; t < TO_; t++)
            acc[t] += w0*xr[t] + w1*xr[t+2] + w2*xr[t+4];
    }
    int ob = ((b*C_ + co)*N_ + n0 + nn)*TO_;
#pragma unroll
    for (int t = 0; t < TO_; t++) g_y[ob + t] = fmaxf(acc[t], 0.f);
}

// ---------------- weight packing ----------------
__global__ void k_pack_qkv(const float* __restrict__ wq, const float* __restrict__ bq,
                           const float* __restrict__ wk, const float* __restrict__ bk,
                           const float* __restrict__ wv, const float* __restrict__ bv) {
    int i = blockIdx.x * 256 + threadIdx.x;
    if (i < 3*64*96) {
        int s = i / 6144, r = i % 6144;
        g_wqkv[i] = (s == 0 ? wq : s == 1 ? wk : wv)[r];
    }
    if (i < 192) {
        int s = i >> 6, r = i & 63;
        g_bqkv[i] = (s == 0 ? bq : s == 1 ? bk : bv)[r];
    }
}
__global__ void k_pack_w3(const float* __restrict__ wadp, const float* __restrict__ badp,
                          const float* __restrict__ w0f) {
    int i = blockIdx.x * 256 + threadIdx.x;
    if (i < 192*128) {
        int row = i >> 7, col = i & 127;
        float v;
        if (row < 64)        v = wadp[i];
        else if (row < 128)  v = (col < 64)  ? w0f[(row-64)*64 + col]       : 0.f;
        else                 v = (col >= 64) ? w0f[(row-128)*64 + col - 64] : 0.f;
        g_w3[i] = v;
    }
    if (i < 192) g_b3[i] = (i < 64) ? badp[i] : 0.f;
}

// ---------------- generic batched conv1x1 GEMM ----------------
__global__ __launch_bounds__(256) void k_conv1x1(
    const float* __restrict__ W, const float* __restrict__ bias,
    const float* __restrict__ X0, int bs0,
    const float* __restrict__ X1, int bs1, int ksplit,
    int K, float* __restrict__ out, int outC, int chOff, int doRelu)
{
    __shared__ float Ws[16][65];
    __shared__ float Xs[16][132];
    int tid = threadIdx.x;
    int b   = blockIdx.z;
    int j0  = blockIdx.x * 128;
    int yb  = blockIdx.y;
    W += yb * 64 * K;
    if (bias) bias += yb * 64;
    chOff += yb * 64;
    int ty  = tid >> 4, tx = tid & 15;

    float acc[4][8];
#pragma unroll
    for (int i = 0; i < 4; i++)
#pragma unroll
        for (int j = 0; j < 8; j++) acc[i][j] = 0.f;

    int wm = tid >> 2, wk4 = (tid & 3) * 4;
    int xr0 = tid >> 5, xc = (tid & 31) * 4;

    for (int k0 = 0; k0 < K; k0 += 16) {
        __syncthreads();
        float4 w4 = *(const float4*)(&W[wm*K + k0 + wk4]);
        Ws[wk4+0][wm] = w4.x; Ws[wk4+1][wm] = w4.y;
        Ws[wk4+2][wm] = w4.z; Ws[wk4+3][wm] = w4.w;
#pragma unroll
        for (int rr = 0; rr < 2; rr++) {
            int r = xr0 + rr*8;
            int k = k0 + r;
            const float* src = (k < ksplit) ? (X0 + (size_t)bs0*b + (size_t)k*NT_)
                                            : (X1 + (size_t)bs1*b + (size_t)(k - ksplit)*NT_);
            *(float4*)(&Xs[r][xc]) = *(const float4*)(src + j0 + xc);
        }
        __syncthreads();
#pragma unroll
        for (int kk = 0; kk < 16; kk++) {
            float a[4], xv[8];
#pragma unroll
            for (int i = 0; i < 4; i++) a[i] = Ws[kk][ty*4 + i];
#pragma unroll
            for (int j = 0; j < 8; j++) xv[j] = Xs[kk][tx*8 + j];
#pragma unroll
            for (int i = 0; i < 4; i++)
#pragma unroll
                for (int j = 0; j < 8; j++) acc[i][j] += a[i]*xv[j];
        }
    }
#pragma unroll
    for (int i = 0; i < 4; i++) {
        int m = ty*4 + i;
        float bv = bias ? bias[m] : 0.f;
        size_t obase = ((size_t)b*outC + chOff + m)*NT_ + j0 + tx*8;
#pragma unroll
        for (int j = 0; j < 8; j++) {
            float v = acc[i][j] + bv;
            if (doRelu) v = fmaxf(v, 0.f);
            out[obase + j] = v;
        }
    }
}

// ---------------- fused masked MHA ----------------
__global__ __launch_bounds__(256) void k_attn() {
    __shared__ float sbuf[8][880];
    int warp = threadIdx.x >> 5, lane = threadIdx.x & 31;
    int g = blockIdx.x * 8 + warp;
    int b = g >> 13;
    int h = (g >> 10) & 7;
    int n = g & 1023;
    float* q = sbuf[warp];
    float* k = q + 160;
    float* v = k + 160;
    float* S = v + 160;

    size_t base = (size_t)(b*192)*NT_ + n*TO_;
    for (int idx = lane; idx < 160; idx += 32) {
        int d = idx / TO_, t = idx % TO_;
        size_t co = (size_t)(h*8 + d)*NT_ + t;
        q[idx] = g_qkv[base + co];
        k[idx] = g_qkv[base + (size_t)64*NT_ + co];
        v[idx] = g_qkv[base + (size_t)128*NT_ + co];
    }
    __syncwarp();
    for (int idx = lane; idx < 400; idx += 32) {
        int t = idx / TO_, s = idx % TO_;
        if (s <= t) {
            float acc = 0.f;
#pragma unroll
            for (int d = 0; d < 8; d++) acc += q[d*TO_ + t] * k[d*TO_ + s];
            S[idx] = acc * 0.35355339059327373f;
        }
    }
    __syncwarp();
    if (lane < TO_) {
        int t = lane;
        float mx = -1e30f;
        for (int s = 0; s <= t; s++) mx = fmaxf(mx, S[t*TO_ + s]);
        float sum = 0.f;
        for (int s = 0; s <= t; s++) { float e = __expf(S[t*TO_ + s] - mx); S[t*TO_ + s] = e; sum += e; }
        float inv = 1.f / sum;
        for (int s = 0; s <= t; s++) S[t*TO_ + s] *= inv;
    }
    __syncwarp();
    size_t obase = (size_t)(b*C_)*NT_ + n*TO_;
    for (int idx = lane; idx < 160; idx += 32) {
        int d = idx / TO_, t = idx % TO_;
        float acc = 0.f;
        for (int s = 0; s <= t; s++) acc += S[t*TO_ + s] * v[d*TO_ + s];
        g_att[obase + (size_t)(h*8 + d)*NT_ + t] = acc;
    }
}

// ---------------- split A into bf16 hi/lo ----------------
__global__ void k_split_A(const float* __restrict__ A0, const float* __restrict__ A1,
                          const float* __restrict__ A2, const float* __restrict__ A3) {
    int i = blockIdx.x * 256 + threadIdx.x;         // 4*1024*1024
    int z = i >> 20, r = i & 1048575;
    const float* A = (z == 0) ? A0 : (z == 1) ? A1 : (z == 2) ? A2 : A3;
    float v = A[r];
    __nv_bfloat16 h = __float2bfloat16(v);
    g_Ah[i] = h;
    g_Al[i] = __float2bfloat16(v - __bfloat162float(h));
}

// ---------------- split x2: cat0 ch0-63 -> cat1 copy + [j][k] bf16 hi/lo ----------------
__global__ void k_split_x() {
    int i = blockIdx.x * 256 + threadIdx.x;         // 20480*1024
    int j = i >> 10, n = i & 1023;
    int b = j / 1280, r = j % 1280, c = r / 20, t = r % 20;
    size_t src = (size_t)(b*192 + c)*NT_ + n*20 + t;
    float v = g_cat0[src];
    g_cat1[src] = v;
    __nv_bfloat16 h = __float2bfloat16(v);
    g_xth[i] = h;
    g_xtl[i] = __float2bfloat16(v - __bfloat162float(h));
}

// ---------------- tensor-core nconv ----------------
// D[128m x 256j] = sum_k A[m][k] * Xt[j][k], split-bf16 x3, K=1024 in 16 chunks of 64.
#define STAGE_BYTES 98304
#define SMEM_TOTAL  (1024 + 2*STAGE_BYTES)

__device__ __forceinline__ void load_chunk(int k0, uint32_t sbase,
                                           const __nv_bfloat16* Ah, const __nv_bfloat16* Al,
                                           int m0, int j0, int tid) {
    for (int g = tid; g < 6144; g += 256) {
        uint32_t dst; const void* src;
        if (g < 2048) {
            int part = g >> 10;
            int gg = g & 1023;
            int r = gg >> 3, c8 = gg & 7;
            const __nv_bfloat16* Ab = part ? Al : Ah;
            src = Ab + (size_t)(m0 + r)*1024 + k0 + c8*8;
            dst = sbase + part*16384 + SWZ(r*128 + c8*16);
        } else {
            int part = (g - 2048) >> 11;
            int gg = (g - 2048) & 2047;
            int r = gg >> 3, c8 = gg & 7;
            const __nv_bfloat16* Xb = part ? g_xtl : g_xth;
            src = Xb + (size_t)(j0 + r)*1024 + k0 + c8*8;
            dst = sbase + 32768 + part*32768 + SWZ(r*128 + c8*16);
        }
        cpa16(dst, src);
    }
}

__global__ __launch_bounds__(256) void k_nconv_tc() {
    extern __shared__ char smem[];
    int tid = threadIdx.x, wid = tid >> 5, lane = tid & 31;
    int j0 = blockIdx.x * 256, m0 = blockIdx.y * 128, z = blockIdx.z;
    const __nv_bfloat16* Ah = g_Ah + (size_t)z*1024*1024;
    const __nv_bfloat16* Al = g_Al + (size_t)z*1024*1024;
    float* Dt = (float*)(smem + 1024);          // [256 cols][129]

#ifdef TC_PATH
    uint32_t sb = smem_u32(smem);
    if (wid == 0) TCGEN05_ALLOC(sb, 256);
    if (tid == 0) { MBARRIER_INIT(sb+8, 1); MBARRIER_INIT(sb+16, 1); }
    __syncthreads();
    uint32_t tmem;
    asm volatile("ld.shared.b32 %0, [%1];" : "=r"(tmem) : "r"(sb));
    uint32_t buf_base = sb + 1024;

    // prologue: chunk 0 -> buf 0
    load_chunk(0, buf_base, Ah, Al, m0, j0, tid);
    cpa_commit();

    int ph0 = 0, ph1 = 0;
    for (int ch = 0; ch < 16; ch++) {
        int buf = ch & 1;
        if (ch + 1 < 16) {
            int nb = 1 - buf;
            if (ch >= 1) {
                MBARRIER_WAIT_PARITY(sb + 8 + 8*nb, (nb == 0) ? ph0 : ph1);
                if (nb == 0) ph0 ^= 1; else ph1 ^= 1;
            }
            load_chunk((ch+1)*64, buf_base + STAGE_BYTES*nb, Ah, Al, m0, j0, tid);
            cpa_commit();
            cpa_wait1();
        } else {
            cpa_wait0();
        }
        __syncthreads();
        if (wid == 0) {
            asm volatile("fence.proxy.async.shared::cta;" ::: "memory");
            if (elect1()) {
                uint32_t s0 = buf_base + STAGE_BYTES*buf;
                uint64_t ah = make_desc(s0);
                uint64_t al = make_desc(s0 + 16384);
                uint64_t xh = make_desc(s0 + 32768);
                uint64_t xl = make_desc(s0 + 65536);
#pragma unroll
                for (int ks = 0; ks < 4; ks++) {
                    mma_f16_ss_cg1(tmem, ah + 2*ks, xh + 2*ks, IDESC_NC, !(ch == 0 && ks == 0));
                    mma_f16_ss_cg1(tmem, ah + 2*ks, xl + 2*ks, IDESC_NC, true);
                    mma_f16_ss_cg1(tmem, al + 2*ks, xh + 2*ks, IDESC_NC, true);
                }
                TCGEN05_COMMIT(sb + 8 + 8*buf);
            }
        }
    }
    MBARRIER_WAIT_PARITY(sb + 16, ph1);
    TCGEN05_FENCE_AFTER();

    // TMEM -> SMEM (transposed, padded)
    {
        int sub = wid & 3, half = wid >> 2;
        int m = sub*32 + lane;
#pragma unroll
        for (int i = 0; i < 4; i++) {
            uint32_t r[32];
            int cb = half*128 + i*32;
            TCGEN05_LD_32X32B_X32(r, tmem + cb);
            TCGEN05_WAIT_LD();
#pragma unroll
            for (int c = 0; c < 32; c++) Dt[(cb + c)*129 + m] = __uint_as_float(r[c]);
        }
    }
    __syncthreads();
    if (tid == 0) { MBARRIER_INVAL(sb+8); MBARRIER_INVAL(sb+16); }
    if (wid == 0) { TCGEN05_RELINQ(); TCGEN05_DEALLOC(tmem, 256); }
    __syncthreads();
#else
    // ---- portable FFMA fallback (used only if the sm_103a cubin is absent) ----
    float* As = (float*)(smem + 1024 + 256*129*4);  // [8][132]
    float* Xs = As + 8*132;                         // [8][132]
    int ty = tid >> 4, tx = tid & 15;
    for (int jp = 0; jp < 2; jp++) {
        float acc[8][8];
#pragma unroll
        for (int i = 0; i < 8; i++)
#pragma unroll
            for (int j = 0; j < 8; j++) acc[i][j] = 0.f;
        for (int k0 = 0; k0 < 1024; k0 += 8) {
            __syncthreads();
            for (int idx = tid; idx < 2048; idx += 256) {
                int half = idx >> 10;
                int e = idx & 1023;
                int row = e >> 3, kk = e & 7;
                if (half == 0) {
                    size_t o = (size_t)(m0 + row)*1024 + k0 + kk;
                    As[kk*132 + row] = __bfloat162float(Ah[o]) + __bfloat162float(Al[o]);
                } else {
                    size_t o = (size_t)(j0 + jp*128 + row)*1024 + k0 + kk;
                    Xs[kk*132 + row] = __bfloat162float(g_xth[o]) + __bfloat162float(g_xtl[o]);
                }
            }
            __syncthreads();
#pragma unroll
            for (int kk = 0; kk < 8; kk++) {
                float a[8], xv[8];
#pragma unroll
                for (int i = 0; i < 8; i++) a[i] = As[kk*132 + ty*8 + i];
#pragma unroll
                for (int j = 0; j < 8; j++) xv[j] = Xs[kk*132 + tx*8 + j];
#pragma unroll
                for (int i = 0; i < 8; i++)
#pragma unroll
                    for (int j = 0; j < 8; j++) acc[i][j] += a[i]*xv[j];
            }
        }
        __syncthreads();
#pragma unroll
        for (int i = 0; i < 8; i++)
#pragma unroll
            for (int j = 0; j < 8; j++)
                Dt[(jp*128 + tx*8 + j)*129 + ty*8 + i] = acc[i][j];
    }
    __syncthreads();
#endif

    // common epilogue: Dt -> global scatter
    int c = tid;
    int j = j0 + c;
    int bc = j / TO_, t = j - bc*TO_;
    int bi = bc >> 6, ci = bc & 63;
    float* dest = (z < 2) ? g_cat0 : g_cat1;
    int chBase = (z & 1) ? 128 : 64;
    size_t obase = (size_t)(bi*192 + chBase + ci)*NT_ + (size_t)m0*TO_ + t;
#pragma unroll 4
    for (int mm = 0; mm < 128; mm++)
        dest[obase + (size_t)mm*TO_] = Dt[c*129 + mm];
}

// ---------------- micro fusion ----------------
__global__ void k_fusion(float* __restrict__ out) {
    int p = blockIdx.x * 256 + threadIdx.x;       // B*NT
    int b = p / NT_, j = p % NT_;
    size_t base = (size_t)b*192*NT_ + j;
    float s0 = 0.f, s1 = 0.f;
    for (int c = 0; c < C_; c++) {
        float uu = g_qkv[base + (size_t)c*NT_];
        s0 += g_qkv[base + (size_t)(64 + c)*NT_]  * uu;
        s1 += g_qkv[base + (size_t)(128 + c)*NT_] * uu;
    }
    float m  = fmaxf(s0, s1);
    float e0 = __expf(s0 - m), e1 = __expf(s1 - m);
    float inv = 1.f / (e0 + e1);
    float a0 = e0 * inv, a1 = e1 * inv;
    size_t ob = (size_t)b*C_*NT_ + j;
    for (int c = 0; c < C_; c++) {
        out[ob + (size_t)c*NT_] = a0 * g_qkv[base + (size_t)(64 + c)*NT_]
                                + a1 * g_qkv[base + (size_t)(128 + c)*NT_];
    }
}

// ---------------- launch ----------------
extern "C" void kernel_launch(void* const* d_in, const int* in_sizes, int n_in,
                              void* d_out, int out_size) {
    const float* x    = (const float*)d_in[0];
    const float* tem  = (const float*)d_in[1];
    const float* A0   = (const float*)d_in[2];
    const float* A1   = (const float*)d_in[3];
    const float* A2   = (const float*)d_in[4];
    const float* A3   = (const float*)d_in[5];
    const float* w_tc = (const float*)d_in[6];
    const float* b_tc = (const float*)d_in[7];
    const float* wq   = (const float*)d_in[8];
    const float* bq   = (const float*)d_in[9];
    const float* wk   = (const float*)d_in[10];
    const float* bk   = (const float*)d_in[11];
    const float* wv   = (const float*)d_in[12];
    const float* bv   = (const float*)d_in[13];
    const float* wo   = (const float*)d_in[14];
    const float* bo   = (const float*)d_in[15];
    const float* wg0  = (const float*)d_in[16];
    const float* bg0  = (const float*)d_in[17];
    const float* wg1  = (const float*)d_in[18];
    const float* bg1  = (const float*)d_in[19];
    const float* wadp = (const float*)d_in[20];
    const float* badp = (const float*)d_in[21];
    const float* w0f  = (const float*)d_in[22];
    float* out = (float*)d_out;

    float *p_tem20, *p_y, *p_qkv, *p_att, *p_cat0, *p_cat1, *p_h01, *p_wqkv, *p_bqkv, *p_w3, *p_b3;
    cudaGetSymbolAddress((void**)&p_tem20, g_tem20);
    cudaGetSymbolAddress((void**)&p_y,     g_y);
    cudaGetSymbolAddress((void**)&p_qkv,   g_qkv);
    cudaGetSymbolAddress((void**)&p_att,   g_att);
    cudaGetSymbolAddress((void**)&p_cat0,  g_cat0);
    cudaGetSymbolAddress((void**)&p_cat1,  g_cat1);
    cudaGetSymbolAddress((void**)&p_h01,   g_h01);
    cudaGetSymbolAddress((void**)&p_wqkv,  g_wqkv);
    cudaGetSymbolAddress((void**)&p_bqkv,  g_bqkv);
    cudaGetSymbolAddress((void**)&p_w3,    g_w3);
    cudaGetSymbolAddress((void**)&p_b3,    g_b3);

    cudaFuncSetAttribute(k_nconv_tc, cudaFuncAttributeMaxDynamicSharedMemorySize, SMEM_TOTAL);

    // prep
    k_slice_tem<<<(B_*CIN_*NT_)/256, 256>>>(tem);
    k_pack_qkv<<<72, 256>>>(wq, bq, wk, bk, wv, bv);
    k_pack_w3<<<96, 256>>>(wadp, badp, w0f);
    k_split_A<<<(4*1024*1024)/256, 256>>>(A0, A1, A2, A3);
    // temporal conv
    k_tc<<<B_*N_/NPB, 256>>>(x, w_tc, b_tc);
    // fused QKV
    k_conv1x1<<<dim3(160, 3, B_), 256>>>(p_wqkv, p_bqkv, p_y, C_*NT_, p_tem20, CIN_*NT_, 64, 96,
                                         p_qkv, 192, 0, 0);
    // attention
    k_attn<<<B_*8*N_/8, 256>>>();
    // WO + relu -> cat0 ch0-63
    k_conv1x1<<<dim3(160, 1, B_), 256>>>(wo, bo, p_att, C_*NT_, p_att, 0, 64, 64,
                                         p_cat0, 192, 0, 1);
    // split x2 into cat1 copy + bf16 hi/lo [j][k]
    k_split_x<<<(20480*1024)/256, 256>>>();
    // tensor-core graph diffusion
    k_nconv_tc<<<dim3(80, 8, 4), 256, SMEM_TOTAL>>>();
    // h0, h1 (K=192) + relu
    k_conv1x1<<<dim3(160, 1, B_), 256>>>(wg0, bg0, p_cat0, 192*NT_, p_cat0, 0, 192, 192,
                                         p_h01, 128, 0, 1);
    k_conv1x1<<<dim3(160, 1, B_), 256>>>(wg1, bg1, p_cat1, 192*NT_, p_cat1, 0, 192, 192,
                                         p_h01, 128, 64, 1);
    // fused [u | h0f | h1f] -> g_qkv
    k_conv1x1<<<dim3(160, 3, B_), 256>>>(p_w3, p_b3, p_h01, 128*NT_, p_h01, 0, 128, 128,
                                         p_qkv, 192, 0, 0);
    // fusion -> out
    k_fusion<<<(B_*NT_)/256, 256>>>(out);
}